// round 14
// baseline (speedup 1.0000x reference)
#include <cuda_runtime.h>
#include <cuda_fp16.h>
#include <cstdint>

#define B_DIM   8
#define N_NODES 100000
#define N_EDGES 3200000
#define E_HALF  (N_EDGES / 2)
#define TB      256

// Node record: 16 B = y[0..7] as 8 halfs (uint4)
__device__ __align__(16) unsigned int g_rec[N_NODES * 4];   // 1.6 MB
__device__ float  g_deg[N_NODES];                           // 400 KB
__device__ __half g_acc[N_NODES * 8];                       // 1.6 MB, [N][8] half

// Grid barrier state (persists across graph replays; gen monotonically grows)
__device__ unsigned int g_count = 0;
__device__ unsigned int g_gen   = 0;

// Bit-cast helpers
__device__ __forceinline__ unsigned int h2u(__half2 h) {
    unsigned int u;
    *reinterpret_cast<__half2*>(&u) = h;
    return u;
}
__device__ __forceinline__ __half2 u2h(unsigned int u) {
    return *reinterpret_cast<__half2*>(&u);
}

// One-wave grid barrier (all blocks co-resident by construction)
__device__ __forceinline__ void grid_barrier(unsigned nblocks) {
    __syncthreads();
    if (threadIdx.x == 0) {
        __threadfence();
        unsigned gen = *(volatile unsigned*)&g_gen;
        if (atomicAdd(&g_count, 1u) == nblocks - 1u) {
            g_count = 0;
            __threadfence();
            *(volatile unsigned*)&g_gen = gen + 1u;
        } else {
            while (*(volatile unsigned*)&g_gen == gen) { }
            __threadfence();
        }
    }
    __syncthreads();
}

__device__ __forceinline__ void edge_body(int n0, uint4 A, uint4 Bv, float w) {
    __half2 s2 = __float2half2_rn(w);
    __half2 z  = __float2half2_rn(0.0f);
    unsigned int u0 = h2u(__hmul2(__hmax2(__hsub2(u2h(A.x), u2h(Bv.x)), z), s2));
    unsigned int u1 = h2u(__hmul2(__hmax2(__hsub2(u2h(A.y), u2h(Bv.y)), z), s2));
    unsigned int u2 = h2u(__hmul2(__hmax2(__hsub2(u2h(A.z), u2h(Bv.z)), z), s2));
    unsigned int u3 = h2u(__hmul2(__hmax2(__hsub2(u2h(A.w), u2h(Bv.w)), z), s2));
    if (u0 | u1 | u2 | u3) {
        asm volatile("red.global.add.noftz.v4.f16x2 [%0], {%1, %2, %3, %4};"
                     :: "l"(g_acc + (size_t)n0 * 8),
                        "r"(u0), "r"(u1), "r"(u2), "r"(u3)
                     : "memory");
    }
}

// ---------------------------------------------------------------------------
// Persistent kernel: init -> barrier -> edges(+deg) -> barrier -> output
// ---------------------------------------------------------------------------
__global__ void __launch_bounds__(TB, 8)
persistent_kernel(const float* __restrict__ y,
                  const float* __restrict__ attr,
                  const float* __restrict__ dist_w,
                  const int* __restrict__ edge_index,
                  float* __restrict__ out,
                  unsigned nblocks) {
    unsigned tid    = blockIdx.x * TB + threadIdx.x;
    unsigned stride = nblocks * TB;

    // ---- Phase 1: zero deg/acc, build half records from y [B,N]
    for (unsigned n = tid; n < N_NODES; n += stride) {
        g_deg[n] = 0.0f;
        reinterpret_cast<uint4*>(g_acc)[n] = make_uint4(0u, 0u, 0u, 0u);
        float v0 = y[0 * N_NODES + n];
        float v1 = y[1 * N_NODES + n];
        float v2 = y[2 * N_NODES + n];
        float v3 = y[3 * N_NODES + n];
        float v4 = y[4 * N_NODES + n];
        float v5 = y[5 * N_NODES + n];
        float v6 = y[6 * N_NODES + n];
        float v7 = y[7 * N_NODES + n];
        __half2 p0 = __floats2half2_rn(v0, v1);
        __half2 p1 = __floats2half2_rn(v2, v3);
        __half2 p2 = __floats2half2_rn(v4, v5);
        __half2 p3 = __floats2half2_rn(v6, v7);
        reinterpret_cast<uint4*>(g_rec)[n] =
            make_uint4(h2u(p0), h2u(p1), h2u(p2), h2u(p3));
    }

    grid_barrier(nblocks);

    // ---- Phase 2: per edge: deg RED + weighted-diff RED (2 edges per iter)
    const uint4* rec = reinterpret_cast<const uint4*>(g_rec);
    for (unsigned t = tid; t < E_HALF; t += stride) {
        unsigned eA = t;
        unsigned eB = t + E_HALF;

        int a0 = edge_index[eA];
        int a1 = edge_index[N_EDGES + eA];
        int b0 = edge_index[eB];
        int b1 = edge_index[N_EDGES + eB];

        uint4 Aa = rec[a0];
        uint4 Ab = rec[a1];
        uint4 Ba = rec[b0];
        uint4 Bb = rec[b1];

        float atA = attr[eA];
        float atB = attr[eB];
        float wA  = rsqrtf(1.0f + __expf(-dist_w[eA]));
        float wB  = rsqrtf(1.0f + __expf(-dist_w[eB]));

        atomicAdd(&g_deg[a0], atA);
        atomicAdd(&g_deg[b0], atB);

        edge_body(a0, Aa, Ab, wA);
        edge_body(b0, Ba, Bb, wB);
    }

    grid_barrier(nblocks);

    // ---- Phase 3: out[b,n] = 1 - acc[n,b] / deg[n]^2
    for (unsigned n = tid; n < N_NODES; n += stride) {
        float d = g_deg[n];
        float inv = 1.0f / (d * d);
        uint4 a = reinterpret_cast<const uint4*>(g_acc)[n];
        float2 f0 = __half22float2(u2h(a.x));
        float2 f1 = __half22float2(u2h(a.y));
        float2 f2 = __half22float2(u2h(a.z));
        float2 f3 = __half22float2(u2h(a.w));
        out[0 * N_NODES + n] = 1.0f - inv * f0.x;
        out[1 * N_NODES + n] = 1.0f - inv * f0.y;
        out[2 * N_NODES + n] = 1.0f - inv * f1.x;
        out[3 * N_NODES + n] = 1.0f - inv * f1.y;
        out[4 * N_NODES + n] = 1.0f - inv * f2.x;
        out[5 * N_NODES + n] = 1.0f - inv * f2.y;
        out[6 * N_NODES + n] = 1.0f - inv * f3.x;
        out[7 * N_NODES + n] = 1.0f - inv * f3.y;
    }
}

// ---------------------------------------------------------------------------
extern "C" void kernel_launch(void* const* d_in, const int* in_sizes, int n_in,
                              void* d_out, int out_size) {
    const float* y    = (const float*)d_in[0];
    const float* attr = (const float*)d_in[2];
    const float* dw   = (const float*)d_in[3];
    const int*   ei   = (const int*)d_in[4];
    float* out = (float*)d_out;

    // Exactly-one-wave grid: guaranteed co-residency for the spin barrier.
    int dev = 0, sms = 148, per_sm = 0;
    cudaGetDevice(&dev);
    cudaDeviceGetAttribute(&sms, cudaDevAttrMultiProcessorCount, dev);
    cudaOccupancyMaxActiveBlocksPerMultiprocessor(&per_sm, persistent_kernel, TB, 0);
    if (per_sm < 1) per_sm = 1;
    if (per_sm > 8) per_sm = 8;
    unsigned nblocks = (unsigned)(sms * per_sm);

    persistent_kernel<<<nblocks, TB>>>(y, attr, dw, ei, out, nblocks);
}

// round 17
// speedup vs baseline: 1.1019x; 1.1019x over previous
#include <cuda_runtime.h>
#include <cuda_fp16.h>
#include <cstdint>

#define B_DIM   8
#define N_NODES 100000
#define N_EDGES 3200000
#define E_HALF  (N_EDGES / 2)
#define TB      256

// Node record: 16 B = y[0..7] as 8 halfs (uint4)
__device__ __align__(16) unsigned int g_rec[N_NODES * 4];   // 1.6 MB
__device__ float  g_deg[N_NODES];                           // 400 KB (zero-init; out_kernel rezeroes)
__device__ __half g_acc[N_NODES * 8];                       // 1.6 MB (zero-init; out_kernel rezeroes)

// Bit-cast helpers
__device__ __forceinline__ unsigned int h2u(__half2 h) {
    unsigned int u;
    *reinterpret_cast<__half2*>(&u) = h;
    return u;
}
__device__ __forceinline__ __half2 u2h(unsigned int u) {
    return *reinterpret_cast<__half2*>(&u);
}

// ---------------------------------------------------------------------------
// K1: build half records from y [B,N]  (acc/deg zeroing handled by K3)
// ---------------------------------------------------------------------------
__global__ void init_kernel(const float* __restrict__ y) {
    int n = blockIdx.x * blockDim.x + threadIdx.x;
    if (n >= N_NODES) return;
    float v0 = y[0 * N_NODES + n];
    float v1 = y[1 * N_NODES + n];
    float v2 = y[2 * N_NODES + n];
    float v3 = y[3 * N_NODES + n];
    float v4 = y[4 * N_NODES + n];
    float v5 = y[5 * N_NODES + n];
    float v6 = y[6 * N_NODES + n];
    float v7 = y[7 * N_NODES + n];
    __half2 p0 = __floats2half2_rn(v0, v1);
    __half2 p1 = __floats2half2_rn(v2, v3);
    __half2 p2 = __floats2half2_rn(v4, v5);
    __half2 p3 = __floats2half2_rn(v6, v7);
    reinterpret_cast<uint4*>(g_rec)[n] =
        make_uint4(h2u(p0), h2u(p1), h2u(p2), h2u(p3));
}

// ---------------------------------------------------------------------------
// K2 (fused, PDL consumer): per edge
//   deg[n0] += attr[e]                                   (f32 RED)
//   acc[n0][b] += sqrt(sigmoid(dw)) * max(y[b,n0]-y[b,n1], 0)  (f16x2 v4 RED)
// 2 edges per thread for MLP. 4 scattered line-touches per edge (floor).
// ---------------------------------------------------------------------------
__device__ __forceinline__ void edge_body(int n0, uint4 A, uint4 Bv, float w) {
    __half2 s2 = __float2half2_rn(w);
    __half2 z  = __float2half2_rn(0.0f);
    unsigned int u0 = h2u(__hmul2(__hmax2(__hsub2(u2h(A.x), u2h(Bv.x)), z), s2));
    unsigned int u1 = h2u(__hmul2(__hmax2(__hsub2(u2h(A.y), u2h(Bv.y)), z), s2));
    unsigned int u2 = h2u(__hmul2(__hmax2(__hsub2(u2h(A.z), u2h(Bv.z)), z), s2));
    unsigned int u3 = h2u(__hmul2(__hmax2(__hsub2(u2h(A.w), u2h(Bv.w)), z), s2));
    if (u0 | u1 | u2 | u3) {
        asm volatile("red.global.add.noftz.v4.f16x2 [%0], {%1, %2, %3, %4};"
                     :: "l"(g_acc + (size_t)n0 * 8),
                        "r"(u0), "r"(u1), "r"(u2), "r"(u3)
                     : "memory");
    }
}

__global__ void fused_kernel(const int* __restrict__ edge_index,
                             const float* __restrict__ attr,
                             const float* __restrict__ dist_w) {
#if __CUDA_ARCH__ >= 900
    cudaGridDependencySynchronize();
#endif
    int t = blockIdx.x * blockDim.x + threadIdx.x;
    if (t >= E_HALF) return;
    int eA = t;
    int eB = t + E_HALF;

    int a0 = edge_index[eA];
    int a1 = edge_index[N_EDGES + eA];
    int b0 = edge_index[eB];
    int b1 = edge_index[N_EDGES + eB];

    const uint4* rec = reinterpret_cast<const uint4*>(g_rec);
    uint4 Aa = rec[a0];
    uint4 Ab = rec[a1];
    uint4 Ba = rec[b0];
    uint4 Bb = rec[b1];

    float atA = attr[eA];
    float atB = attr[eB];
    float wA  = rsqrtf(1.0f + __expf(-dist_w[eA]));
    float wB  = rsqrtf(1.0f + __expf(-dist_w[eB]));

    atomicAdd(&g_deg[a0], atA);
    atomicAdd(&g_deg[b0], atB);

    edge_body(a0, Aa, Ab, wA);
    edge_body(b0, Ba, Bb, wB);
}

// ---------------------------------------------------------------------------
// K3 (PDL consumer): out[b,n] = 1 - acc[n,b]/deg[n]^2, then rezero acc/deg
// so the next call starts from zeros (globals are zero-init on load).
// ---------------------------------------------------------------------------
__global__ void out_kernel(float* __restrict__ out) {
#if __CUDA_ARCH__ >= 900
    cudaGridDependencySynchronize();
#endif
    int n = blockIdx.x * blockDim.x + threadIdx.x;
    if (n >= N_NODES) return;
    float d = g_deg[n];
    float inv = 1.0f / (d * d);
    uint4 a = reinterpret_cast<const uint4*>(g_acc)[n];
    // rezero for next call
    g_deg[n] = 0.0f;
    reinterpret_cast<uint4*>(g_acc)[n] = make_uint4(0u, 0u, 0u, 0u);

    float2 f0 = __half22float2(u2h(a.x));
    float2 f1 = __half22float2(u2h(a.y));
    float2 f2 = __half22float2(u2h(a.z));
    float2 f3 = __half22float2(u2h(a.w));
    out[0 * N_NODES + n] = 1.0f - inv * f0.x;
    out[1 * N_NODES + n] = 1.0f - inv * f0.y;
    out[2 * N_NODES + n] = 1.0f - inv * f1.x;
    out[3 * N_NODES + n] = 1.0f - inv * f1.y;
    out[4 * N_NODES + n] = 1.0f - inv * f2.x;
    out[5 * N_NODES + n] = 1.0f - inv * f2.y;
    out[6 * N_NODES + n] = 1.0f - inv * f3.x;
    out[7 * N_NODES + n] = 1.0f - inv * f3.y;
}

// ---------------------------------------------------------------------------
extern "C" void kernel_launch(void* const* d_in, const int* in_sizes, int n_in,
                              void* d_out, int out_size) {
    const float* y    = (const float*)d_in[0];
    const float* attr = (const float*)d_in[2];
    const float* dw   = (const float*)d_in[3];
    const int*   ei   = (const int*)d_in[4];
    float* out = (float*)d_out;

    init_kernel<<<(N_NODES + TB - 1) / TB, TB>>>(y);

    // PDL: overlap each kernel's launch/ramp with predecessor's drain.
    cudaLaunchAttribute pdl[1];
    pdl[0].id = cudaLaunchAttributeProgrammaticStreamSerialization;
    pdl[0].val.programmaticStreamSerializationAllowed = 1;

    {
        cudaLaunchConfig_t cfg = {};
        cfg.gridDim  = dim3((E_HALF + TB - 1) / TB);
        cfg.blockDim = dim3(TB);
        cfg.stream   = 0;
        cfg.attrs    = pdl;
        cfg.numAttrs = 1;
        cudaLaunchKernelEx(&cfg, fused_kernel, ei, attr, dw);
    }
    {
        cudaLaunchConfig_t cfg = {};
        cfg.gridDim  = dim3((N_NODES + TB - 1) / TB);
        cfg.blockDim = dim3(TB);
        cfg.stream   = 0;
        cfg.attrs    = pdl;
        cfg.numAttrs = 1;
        cudaLaunchKernelEx(&cfg, out_kernel, out);
    }
}